// round 1
// baseline (speedup 1.0000x reference)
#include <cuda_runtime.h>
#include <math.h>

#define BATCH 4
#define SEQ   4096
#define EMB   512

// Scratch (sanctioned: __device__ globals, no runtime allocation)
__device__ float g_q[BATCH * SEQ * EMB];                     // 32 MB
__device__ float g_k[BATCH * SEQ * EMB];                     // 32 MB
__device__ float g_v[BATCH * SEQ * EMB];                     // 32 MB
__device__ float g_s[(size_t)BATCH * SEQ * SEQ];             // 256 MB scores/attn

// ---------------------------------------------------------------------------
// NT GEMM: C[m,n] = sum_k A[m,k] * B[n,k] (+ bias[n])
// A: [M,K] row-major, B: [N,K] row-major, C: [M,N] row-major.
// Tile 64x64, BK=16, 256 threads, 4x4 micro-tile per thread.
// All dims here are multiples of tile sizes -> no bounds checks.
// ---------------------------------------------------------------------------
template <bool BIAS>
__global__ void __launch_bounds__(256)
gemm_nt(const float* __restrict__ A, const float* __restrict__ B,
        const float* __restrict__ bias, float* __restrict__ C,
        int M, int N, int K,
        long strideA, long strideB, long strideC)
{
    __shared__ float As[16 * 64];   // [k][m]
    __shared__ float Bs[16 * 64];   // [k][n]

    const int bz = blockIdx.z;
    A += (long)bz * strideA;
    B += (long)bz * strideB;
    C += (long)bz * strideC;

    const int tid  = threadIdx.x;
    const int tx   = tid & 15;          // 0..15 -> n micro
    const int ty   = tid >> 4;          // 0..15 -> m micro
    const int lrow = tid >> 2;          // 0..63  (load row)
    const int lk4  = (tid & 3) * 4;     // 0,4,8,12 (load k quad)

    const int m0 = blockIdx.y * 64;
    const int n0 = blockIdx.x * 64;

    float acc[4][4];
#pragma unroll
    for (int i = 0; i < 4; i++)
#pragma unroll
        for (int j = 0; j < 4; j++) acc[i][j] = 0.f;

    for (int k0 = 0; k0 < K; k0 += 16) {
        float4 a4 = *reinterpret_cast<const float4*>(A + (long)(m0 + lrow) * K + k0 + lk4);
        float4 b4 = *reinterpret_cast<const float4*>(B + (long)(n0 + lrow) * K + k0 + lk4);
        As[(lk4 + 0) * 64 + lrow] = a4.x;
        As[(lk4 + 1) * 64 + lrow] = a4.y;
        As[(lk4 + 2) * 64 + lrow] = a4.z;
        As[(lk4 + 3) * 64 + lrow] = a4.w;
        Bs[(lk4 + 0) * 64 + lrow] = b4.x;
        Bs[(lk4 + 1) * 64 + lrow] = b4.y;
        Bs[(lk4 + 2) * 64 + lrow] = b4.z;
        Bs[(lk4 + 3) * 64 + lrow] = b4.w;
        __syncthreads();

#pragma unroll
        for (int kk = 0; kk < 16; kk++) {
            float4 av = *reinterpret_cast<const float4*>(&As[kk * 64 + ty * 4]);
            float4 bv = *reinterpret_cast<const float4*>(&Bs[kk * 64 + tx * 4]);
            float am[4] = {av.x, av.y, av.z, av.w};
            float bn[4] = {bv.x, bv.y, bv.z, bv.w};
#pragma unroll
            for (int i = 0; i < 4; i++)
#pragma unroll
                for (int j = 0; j < 4; j++) acc[i][j] = fmaf(am[i], bn[j], acc[i][j]);
        }
        __syncthreads();
    }

    float bb[4] = {0.f, 0.f, 0.f, 0.f};
    if (BIAS) {
#pragma unroll
        for (int j = 0; j < 4; j++) bb[j] = bias[n0 + tx * 4 + j];
    }
#pragma unroll
    for (int i = 0; i < 4; i++) {
        float4 cv;
        cv.x = acc[i][0] + bb[0];
        cv.y = acc[i][1] + bb[1];
        cv.z = acc[i][2] + bb[2];
        cv.w = acc[i][3] + bb[3];
        *reinterpret_cast<float4*>(C + (long)(m0 + ty * 4 + i) * N + n0 + tx * 4) = cv;
    }
}

// ---------------------------------------------------------------------------
// NN GEMM: C[m,n] = sum_k A[m,k] * B[k,n]
// A: [M,K] row-major, B: [K,N] row-major.
// ---------------------------------------------------------------------------
__global__ void __launch_bounds__(256)
gemm_nn(const float* __restrict__ A, const float* __restrict__ B,
        float* __restrict__ C,
        int M, int N, int K,
        long strideA, long strideB, long strideC)
{
    __shared__ float As[16 * 64];   // [k][m]
    __shared__ float Bs[16 * 64];   // [k][n]

    const int bz = blockIdx.z;
    A += (long)bz * strideA;
    B += (long)bz * strideB;
    C += (long)bz * strideC;

    const int tid  = threadIdx.x;
    const int tx   = tid & 15;
    const int ty   = tid >> 4;
    const int lrow = tid >> 2;
    const int lk4  = (tid & 3) * 4;

    // B-tile load mapping: linear float4 index
    const int bkk = tid / 16;           // 0..15 (k row)
    const int bn4 = (tid % 16) * 4;     // 0..60 (n quad)

    const int m0 = blockIdx.y * 64;
    const int n0 = blockIdx.x * 64;

    float acc[4][4];
#pragma unroll
    for (int i = 0; i < 4; i++)
#pragma unroll
        for (int j = 0; j < 4; j++) acc[i][j] = 0.f;

    for (int k0 = 0; k0 < K; k0 += 16) {
        float4 a4 = *reinterpret_cast<const float4*>(A + (long)(m0 + lrow) * K + k0 + lk4);
        As[(lk4 + 0) * 64 + lrow] = a4.x;
        As[(lk4 + 1) * 64 + lrow] = a4.y;
        As[(lk4 + 2) * 64 + lrow] = a4.z;
        As[(lk4 + 3) * 64 + lrow] = a4.w;
        float4 b4 = *reinterpret_cast<const float4*>(B + (long)(k0 + bkk) * N + n0 + bn4);
        *reinterpret_cast<float4*>(&Bs[bkk * 64 + bn4]) = b4;
        __syncthreads();

#pragma unroll
        for (int kk = 0; kk < 16; kk++) {
            float4 av = *reinterpret_cast<const float4*>(&As[kk * 64 + ty * 4]);
            float4 bv = *reinterpret_cast<const float4*>(&Bs[kk * 64 + tx * 4]);
            float am[4] = {av.x, av.y, av.z, av.w};
            float bn[4] = {bv.x, bv.y, bv.z, bv.w};
#pragma unroll
            for (int i = 0; i < 4; i++)
#pragma unroll
                for (int j = 0; j < 4; j++) acc[i][j] = fmaf(am[i], bn[j], acc[i][j]);
        }
        __syncthreads();
    }

#pragma unroll
    for (int i = 0; i < 4; i++) {
        float4 cv = make_float4(acc[i][0], acc[i][1], acc[i][2], acc[i][3]);
        *reinterpret_cast<float4*>(C + (long)(m0 + ty * 4 + i) * N + n0 + tx * 4) = cv;
    }
}

// ---------------------------------------------------------------------------
// Row softmax, in place. One block per row, 256 threads, ncols = 4096.
// ---------------------------------------------------------------------------
__global__ void __launch_bounds__(256)
softmax_rows(float* __restrict__ S)
{
    const long row = blockIdx.x;
    float* p = S + row * (long)SEQ;
    const int tid  = threadIdx.x;
    const int lane = tid & 31;
    const int wid  = tid >> 5;

    float vals[16];
    float m = -3.0e38f;
#pragma unroll
    for (int i = 0; i < 4; i++) {
        float4 v = reinterpret_cast<float4*>(p)[tid + i * 256];
        vals[i * 4 + 0] = v.x; vals[i * 4 + 1] = v.y;
        vals[i * 4 + 2] = v.z; vals[i * 4 + 3] = v.w;
        m = fmaxf(m, fmaxf(fmaxf(v.x, v.y), fmaxf(v.z, v.w)));
    }

    __shared__ float red[8];
#pragma unroll
    for (int off = 16; off > 0; off >>= 1)
        m = fmaxf(m, __shfl_xor_sync(0xffffffffu, m, off));
    if (lane == 0) red[wid] = m;
    __syncthreads();
    float mAll = red[0];
#pragma unroll
    for (int w = 1; w < 8; w++) mAll = fmaxf(mAll, red[w]);
    __syncthreads();

    float s = 0.f;
#pragma unroll
    for (int i = 0; i < 16; i++) {
        vals[i] = __expf(vals[i] - mAll);
        s += vals[i];
    }
#pragma unroll
    for (int off = 16; off > 0; off >>= 1)
        s += __shfl_xor_sync(0xffffffffu, s, off);
    if (lane == 0) red[wid] = s;
    __syncthreads();
    float sAll = 0.f;
#pragma unroll
    for (int w = 0; w < 8; w++) sAll += red[w];
    const float inv = 1.0f / sAll;

#pragma unroll
    for (int i = 0; i < 4; i++) {
        float4 v;
        v.x = vals[i * 4 + 0] * inv; v.y = vals[i * 4 + 1] * inv;
        v.z = vals[i * 4 + 2] * inv; v.w = vals[i * 4 + 3] * inv;
        reinterpret_cast<float4*>(p)[tid + i * 256] = v;
    }
}

// ---------------------------------------------------------------------------
extern "C" void kernel_launch(void* const* d_in, const int* in_sizes, int n_in,
                              void* d_out, int out_size)
{
    const float* q_in = (const float*)d_in[0];
    const float* k_in = (const float*)d_in[1];
    const float* v_in = (const float*)d_in[2];
    const float* Wq   = (const float*)d_in[3];
    const float* bq   = (const float*)d_in[4];
    const float* Wk   = (const float*)d_in[5];
    const float* bk   = (const float*)d_in[6];
    const float* Wv   = (const float*)d_in[7];
    const float* bv   = (const float*)d_in[8];
    float* out = (float*)d_out;

    float *gq, *gk, *gv, *gs;
    cudaGetSymbolAddress((void**)&gq, g_q);
    cudaGetSymbolAddress((void**)&gk, g_k);
    cudaGetSymbolAddress((void**)&gv, g_v);
    cudaGetSymbolAddress((void**)&gs, g_s);

    const int MS = BATCH * SEQ;          // 16384 flattened rows for projections
    dim3 blk(256);

    // 1) QKV projections: [16384,512] @ W^T[512,512] + b
    {
        dim3 grd(EMB / 64, MS / 64, 1);
        gemm_nt<true><<<grd, blk>>>(q_in, Wq, bq, gq, MS, EMB, EMB, 0, 0, 0);
        gemm_nt<true><<<grd, blk>>>(k_in, Wk, bk, gk, MS, EMB, EMB, 0, 0, 0);
        gemm_nt<true><<<grd, blk>>>(v_in, Wv, bv, gv, MS, EMB, EMB, 0, 0, 0);
    }

    // 2) scores[b] = q[b] @ k[b]^T  -> g_s  (batched via blockIdx.z)
    {
        dim3 grd(SEQ / 64, SEQ / 64, BATCH);
        gemm_nt<false><<<grd, blk>>>(gq, gk, nullptr, gs, SEQ, SEQ, EMB,
                                     (long)SEQ * EMB, (long)SEQ * EMB, (long)SEQ * SEQ);
    }

    // 3) row-wise softmax in place
    softmax_rows<<<BATCH * SEQ, blk>>>(gs);

    // 4) out[b] = attn[b] @ v[b]
    {
        dim3 grd(EMB / 64, SEQ / 64, BATCH);
        gemm_nn<<<grd, blk>>>(gs, gv, out, SEQ, EMB, SEQ,
                              (long)SEQ * SEQ, (long)SEQ * EMB, (long)SEQ * EMB);
    }
}

// round 3
// speedup vs baseline: 1.7773x; 1.7773x over previous
#include <cuda_runtime.h>
#include <math.h>

#define BATCH 4
#define SEQ   4096
#define EMB   512

// Scratch (__device__ globals: sanctioned, no runtime allocation)
__device__ float g_q [BATCH * SEQ * EMB];                 // 32 MB  [b*s][e]
__device__ float g_k [BATCH * SEQ * EMB];                 // 32 MB  [b*s][e]
__device__ float g_vt[BATCH * SEQ * EMB];                 // 32 MB  [b][e][s] (transposed)
__device__ float g_s [(size_t)BATCH * SEQ * SEQ];         // 256 MB scores/attn

__device__ __forceinline__ float cvt_tf32(float x) {
    asm("cvt.rna.tf32.f32 %0, %0;" : "+f"(x));
    return x;
}

#define TILE_F 4608   // 128 * 36 floats per shared tile

// ---------------------------------------------------------------------------
// TF32(x2) tensor-core NT GEMM:  C[m,n] = sum_k A[m,k]*B[n,k] (+bias[n])
// Block tile 128x128, BK=32, 256 threads (8 warps, 4m x 2n), warp tile 32x64.
// X2: emulate fp32 via hi/lo split -> 3 mma per fragment (hh + hl + lh).
// TRANSC: scatter C transposed into [b][n][s] layout (V projection).
// ---------------------------------------------------------------------------
template <bool BIAS, bool TRANSC, bool X2>
__global__ void __launch_bounds__(256)
mma_gemm_nt(const float* __restrict__ A, const float* __restrict__ B,
            const float* __restrict__ bias, float* __restrict__ C,
            int K, int lda, int ldb, int ldc,
            long sA, long sB, long sC)
{
    extern __shared__ float smem[];
    float* AsH = smem;
    float* BsH = smem + TILE_F;
    float* AsL = X2 ? smem + 2 * TILE_F : nullptr;
    float* BsL = X2 ? smem + 3 * TILE_F : nullptr;

    const int bz = blockIdx.z;
    A += (long)bz * sA;
    B += (long)bz * sB;
    C += (long)bz * sC;

    const int tid  = threadIdx.x;
    const int lane = tid & 31;
    const int wid  = tid >> 5;
    const int wm   = (wid & 3) * 32;
    const int wn   = (wid >> 2) * 64;
    const int m0   = blockIdx.y * 128;
    const int n0   = blockIdx.x * 128;

    // global load mapping: 256 threads, 4 x float4 each per 128x32 tile
    const int lrow = tid >> 3;          // 0..31
    const int lk4  = (tid & 7) * 4;     // 0..28
    const float* Ag = A + (long)(m0 + lrow) * lda + lk4;
    const float* Bg = B + (long)(n0 + lrow) * ldb + lk4;

    float acc[2][8][4];
#pragma unroll
    for (int i = 0; i < 2; i++)
#pragma unroll
        for (int j = 0; j < 8; j++)
#pragma unroll
            for (int r = 0; r < 4; r++) acc[i][j][r] = 0.f;

    const unsigned aHB = (unsigned)__cvta_generic_to_shared(AsH);
    const unsigned bHB = (unsigned)__cvta_generic_to_shared(BsH);
    const unsigned aLB = X2 ? (unsigned)__cvta_generic_to_shared(AsL) : 0;
    const unsigned bLB = X2 ? (unsigned)__cvta_generic_to_shared(BsL) : 0;
    const int r8 = lane & 7;
    const int hi = (lane >> 3) & 1;
    const int hf = lane >> 4;

    // ldmatrix base offsets (same lane mapping as validated round-2 kernel)
    unsigned aOff[2], bOff[4];
#pragma unroll
    for (int mi = 0; mi < 2; mi++)
        aOff[mi] = ((wm + mi * 16 + r8 + hi * 8) * 36 + hf * 4) << 2;
#pragma unroll
    for (int p = 0; p < 4; p++)
        bOff[p] = ((wn + p * 16 + r8 + hf * 8) * 36 + hi * 4) << 2;

    const int niter = K >> 5;

    float4 sa[4], sb[4];
#pragma unroll
    for (int i = 0; i < 4; i++) {
        sa[i] = *reinterpret_cast<const float4*>(Ag + (long)i * 32 * lda);
        sb[i] = *reinterpret_cast<const float4*>(Bg + (long)i * 32 * ldb);
    }

    for (int it = 0; it < niter; it++) {
        // stage tile: split fp32 -> tf32 hi (+ lo)
#pragma unroll
        for (int i = 0; i < 4; i++) {
            float ah[4] = {cvt_tf32(sa[i].x), cvt_tf32(sa[i].y),
                           cvt_tf32(sa[i].z), cvt_tf32(sa[i].w)};
            float bh[4] = {cvt_tf32(sb[i].x), cvt_tf32(sb[i].y),
                           cvt_tf32(sb[i].z), cvt_tf32(sb[i].w)};
            *reinterpret_cast<float4*>(&AsH[(lrow + i * 32) * 36 + lk4]) =
                make_float4(ah[0], ah[1], ah[2], ah[3]);
            *reinterpret_cast<float4*>(&BsH[(lrow + i * 32) * 36 + lk4]) =
                make_float4(bh[0], bh[1], bh[2], bh[3]);
            if (X2) {
                *reinterpret_cast<float4*>(&AsL[(lrow + i * 32) * 36 + lk4]) =
                    make_float4(cvt_tf32(sa[i].x - ah[0]), cvt_tf32(sa[i].y - ah[1]),
                                cvt_tf32(sa[i].z - ah[2]), cvt_tf32(sa[i].w - ah[3]));
                *reinterpret_cast<float4*>(&BsL[(lrow + i * 32) * 36 + lk4]) =
                    make_float4(cvt_tf32(sb[i].x - bh[0]), cvt_tf32(sb[i].y - bh[1]),
                                cvt_tf32(sb[i].z - bh[2]), cvt_tf32(sb[i].w - bh[3]));
            }
        }
        __syncthreads();

        if (it + 1 < niter) {
            const float* Ap = Ag + (it + 1) * 32;
            const float* Bp = Bg + (it + 1) * 32;
#pragma unroll
            for (int i = 0; i < 4; i++) {
                sa[i] = *reinterpret_cast<const float4*>(Ap + (long)i * 32 * lda);
                sb[i] = *reinterpret_cast<const float4*>(Bp + (long)i * 32 * ldb);
            }
        }

#pragma unroll
        for (int ks = 0; ks < 4; ks++) {
            unsigned aFh[2][4], bFh[8][2];
            unsigned aFl[2][4], bFl[8][2];
#pragma unroll
            for (int mi = 0; mi < 2; mi++) {
                asm volatile(
                    "ldmatrix.sync.aligned.m8n8.x4.shared.b16 {%0,%1,%2,%3}, [%4];"
                    : "=r"(aFh[mi][0]), "=r"(aFh[mi][1]), "=r"(aFh[mi][2]), "=r"(aFh[mi][3])
                    : "r"(aHB + aOff[mi] + ks * 32));
                if (X2) {
                    asm volatile(
                        "ldmatrix.sync.aligned.m8n8.x4.shared.b16 {%0,%1,%2,%3}, [%4];"
                        : "=r"(aFl[mi][0]), "=r"(aFl[mi][1]), "=r"(aFl[mi][2]), "=r"(aFl[mi][3])
                        : "r"(aLB + aOff[mi] + ks * 32));
                }
            }
#pragma unroll
            for (int p = 0; p < 4; p++) {
                unsigned r0, r1, r2, r3;
                asm volatile(
                    "ldmatrix.sync.aligned.m8n8.x4.shared.b16 {%0,%1,%2,%3}, [%4];"
                    : "=r"(r0), "=r"(r1), "=r"(r2), "=r"(r3)
                    : "r"(bHB + bOff[p] + ks * 32));
                bFh[2 * p][0] = r0; bFh[2 * p][1] = r1;
                bFh[2 * p + 1][0] = r2; bFh[2 * p + 1][1] = r3;
                if (X2) {
                    asm volatile(
                        "ldmatrix.sync.aligned.m8n8.x4.shared.b16 {%0,%1,%2,%3}, [%4];"
                        : "=r"(r0), "=r"(r1), "=r"(r2), "=r"(r3)
                        : "r"(bLB + bOff[p] + ks * 32));
                    bFl[2 * p][0] = r0; bFl[2 * p][1] = r1;
                    bFl[2 * p + 1][0] = r2; bFl[2 * p + 1][1] = r3;
                }
            }

#define MMA(aa, bb, mi, nj)                                                   \
    asm volatile(                                                             \
        "mma.sync.aligned.m16n8k8.row.col.f32.tf32.tf32.f32 "                 \
        "{%0,%1,%2,%3}, {%4,%5,%6,%7}, {%8,%9}, {%0,%1,%2,%3};"               \
        : "+f"(acc[mi][nj][0]), "+f"(acc[mi][nj][1]),                         \
          "+f"(acc[mi][nj][2]), "+f"(acc[mi][nj][3])                          \
        : "r"(aa[mi][0]), "r"(aa[mi][1]), "r"(aa[mi][2]), "r"(aa[mi][3]),     \
          "r"(bb[nj][0]), "r"(bb[nj][1]))

#pragma unroll
            for (int mi = 0; mi < 2; mi++)
#pragma unroll
                for (int nj = 0; nj < 8; nj++) {
                    if (X2) {
                        MMA(aFh, bFl, mi, nj);   // hi*lo
                        MMA(aFl, bFh, mi, nj);   // lo*hi
                    }
                    MMA(aFh, bFh, mi, nj);       // hi*hi (last: biggest term)
                }
#undef MMA
        }
        __syncthreads();
    }

    // epilogue
    const int g = lane >> 2;
    const int t = lane & 3;
#pragma unroll
    for (int nj = 0; nj < 8; nj++) {
        const int col = n0 + wn + nj * 8 + t * 2;
        float b0 = 0.f, b1 = 0.f;
        if (BIAS) { b0 = bias[col]; b1 = bias[col + 1]; }
#pragma unroll
        for (int mi = 0; mi < 2; mi++) {
            const int row = m0 + wm + mi * 16 + g;
            float c0 = acc[mi][nj][0] + b0;
            float c1 = acc[mi][nj][1] + b1;
            float c2 = acc[mi][nj][2] + b0;
            float c3 = acc[mi][nj][3] + b1;
            if (!TRANSC) {
                *reinterpret_cast<float2*>(&C[(long)row * ldc + col]) = make_float2(c0, c1);
                *reinterpret_cast<float2*>(&C[(long)(row + 8) * ldc + col]) = make_float2(c2, c3);
            } else {
                const int bb = row >> 12;
                const int s  = row & 4095;
                float* Cb = C + (long)bb * EMB * SEQ + s;
                Cb[(long)col * SEQ]           = c0;
                Cb[(long)(col + 1) * SEQ]     = c1;
                Cb[(long)col * SEQ + 8]       = c2;
                Cb[(long)(col + 1) * SEQ + 8] = c3;
            }
        }
    }
}

// ---------------------------------------------------------------------------
// Row softmax, in place. One block per 4096-col row, 256 threads.
// ---------------------------------------------------------------------------
__global__ void __launch_bounds__(256)
softmax_rows(float* __restrict__ S)
{
    const long row = blockIdx.x;
    float* p = S + row * (long)SEQ;
    const int tid  = threadIdx.x;
    const int lane = tid & 31;
    const int wid  = tid >> 5;

    float vals[16];
    float m = -3.0e38f;
#pragma unroll
    for (int i = 0; i < 4; i++) {
        float4 v = reinterpret_cast<float4*>(p)[tid + i * 256];
        vals[i * 4 + 0] = v.x; vals[i * 4 + 1] = v.y;
        vals[i * 4 + 2] = v.z; vals[i * 4 + 3] = v.w;
        m = fmaxf(m, fmaxf(fmaxf(v.x, v.y), fmaxf(v.z, v.w)));
    }

    __shared__ float red[8];
#pragma unroll
    for (int off = 16; off > 0; off >>= 1)
        m = fmaxf(m, __shfl_xor_sync(0xffffffffu, m, off));
    if (lane == 0) red[wid] = m;
    __syncthreads();
    float mAll = red[0];
#pragma unroll
    for (int w = 1; w < 8; w++) mAll = fmaxf(mAll, red[w]);
    __syncthreads();

    float s = 0.f;
#pragma unroll
    for (int i = 0; i < 16; i++) {
        vals[i] = __expf(vals[i] - mAll);
        s += vals[i];
    }
#pragma unroll
    for (int off = 16; off > 0; off >>= 1)
        s += __shfl_xor_sync(0xffffffffu, s, off);
    if (lane == 0) red[wid] = s;
    __syncthreads();
    float sAll = 0.f;
#pragma unroll
    for (int w = 0; w < 8; w++) sAll += red[w];
    const float inv = 1.0f / sAll;

#pragma unroll
    for (int i = 0; i < 4; i++) {
        float4 v;
        v.x = vals[i * 4 + 0] * inv; v.y = vals[i * 4 + 1] * inv;
        v.z = vals[i * 4 + 2] * inv; v.w = vals[i * 4 + 3] * inv;
        reinterpret_cast<float4*>(p)[tid + i * 256] = v;
    }
}

// ---------------------------------------------------------------------------
extern "C" void kernel_launch(void* const* d_in, const int* in_sizes, int n_in,
                              void* d_out, int out_size)
{
    const float* q_in = (const float*)d_in[0];
    const float* k_in = (const float*)d_in[1];
    const float* v_in = (const float*)d_in[2];
    const float* Wq   = (const float*)d_in[3];
    const float* bq   = (const float*)d_in[4];
    const float* Wk   = (const float*)d_in[5];
    const float* bk   = (const float*)d_in[6];
    const float* Wv   = (const float*)d_in[7];
    const float* bv   = (const float*)d_in[8];
    float* out = (float*)d_out;

    float *gq, *gk, *gvt, *gs;
    cudaGetSymbolAddress((void**)&gq,  g_q);
    cudaGetSymbolAddress((void**)&gk,  g_k);
    cudaGetSymbolAddress((void**)&gvt, g_vt);
    cudaGetSymbolAddress((void**)&gs,  g_s);

    const size_t smemX2 = 4 * TILE_F * sizeof(float);   // 73728 B

    static bool attrDone = false;
    if (!attrDone) {
        cudaFuncSetAttribute(mma_gemm_nt<true,  false, true>,
                             cudaFuncAttributeMaxDynamicSharedMemorySize, (int)smemX2);
        cudaFuncSetAttribute(mma_gemm_nt<true,  true,  true>,
                             cudaFuncAttributeMaxDynamicSharedMemorySize, (int)smemX2);
        cudaFuncSetAttribute(mma_gemm_nt<false, false, true>,
                             cudaFuncAttributeMaxDynamicSharedMemorySize, (int)smemX2);
        attrDone = true;
    }

    dim3 blk(256);

    // 1) projections: [16384,512] @ W^T + b   (V transposed into g_vt)
    {
        dim3 grd(EMB / 128, (BATCH * SEQ) / 128, 1);
        mma_gemm_nt<true, false, true><<<grd, blk, smemX2>>>(
            q_in, Wq, bq, gq, EMB, EMB, EMB, EMB, 0, 0, 0);
        mma_gemm_nt<true, false, true><<<grd, blk, smemX2>>>(
            k_in, Wk, bk, gk, EMB, EMB, EMB, EMB, 0, 0, 0);
        mma_gemm_nt<true, true, true><<<grd, blk, smemX2>>>(
            v_in, Wv, bv, gvt, EMB, EMB, EMB, SEQ, 0, 0, 0);
    }

    // 2) scores[b] = q[b] @ k[b]^T
    {
        dim3 grd(SEQ / 128, SEQ / 128, BATCH);
        mma_gemm_nt<false, false, true><<<grd, blk, smemX2>>>(
            gq, gk, nullptr, gs, EMB, EMB, EMB, SEQ,
            (long)SEQ * EMB, (long)SEQ * EMB, (long)SEQ * SEQ);
    }

    // 3) row softmax in place
    softmax_rows<<<BATCH * SEQ, blk>>>(gs);

    // 4) out[b] = attn[b] @ v[b]   (B = vT[b], NT form)
    {
        dim3 grd(EMB / 128, SEQ / 128, BATCH);
        mma_gemm_nt<false, false, true><<<grd, blk, smemX2>>>(
            gs, gvt, nullptr, out, SEQ, SEQ, SEQ, EMB,
            (long)SEQ * SEQ, (long)EMB * SEQ, (long)SEQ * EMB);
    }
}